// round 13
// baseline (speedup 1.0000x reference)
#include <cuda_runtime.h>
#include <cstdint>

#define Bq 8
#define Cc 256
#define NQ 4096
#define NK 4096
#define KK 8

// Scratch (device globals — no allocation allowed)
__device__ float g_kf_t[(size_t)Bq * NK * Cc];   // key_features transposed [b, m, c]
__device__ int   g_idx[(size_t)Bq * NQ * KK];    // knn indices

// ---------------------------------------------------------------------------
// packed-f32x2 helpers (two independent IEEE fp32 ops -> bitwise == scalar)
// ---------------------------------------------------------------------------
__device__ __forceinline__ uint32_t smem_u32(const void* p) {
    uint32_t r;
    asm("{ .reg .u64 t; cvta.to.shared.u64 t, %1; cvt.u32.u64 %0, t; }"
        : "=r"(r) : "l"(p));
    return r;
}
__device__ __forceinline__ void lds_v2u64(uint64_t& a, uint64_t& b, uint32_t addr) {
    asm volatile("ld.shared.v2.u64 {%0, %1}, [%2];" : "=l"(a), "=l"(b) : "r"(addr));
}
__device__ __forceinline__ uint64_t pack2(float lo, float hi) {
    uint64_t r;
    asm("mov.b64 %0, {%1, %2};" : "=l"(r) : "f"(lo), "f"(hi));
    return r;
}
__device__ __forceinline__ void unpack2(float& lo, float& hi, uint64_t v) {
    asm("mov.b64 {%0, %1}, %2;" : "=f"(lo), "=f"(hi) : "l"(v));
}
__device__ __forceinline__ uint64_t mul2(uint64_t a, uint64_t b) {
    uint64_t r; asm("mul.rn.f32x2 %0, %1, %2;" : "=l"(r) : "l"(a), "l"(b)); return r;
}
__device__ __forceinline__ uint64_t fma2(uint64_t a, uint64_t b, uint64_t c) {
    uint64_t r; asm("fma.rn.f32x2 %0, %1, %2, %3;" : "=l"(r) : "l"(a), "l"(b), "l"(c)); return r;
}
__device__ __forceinline__ uint64_t add2(uint64_t a, uint64_t b) {
    uint64_t r; asm("add.rn.f32x2 %0, %1, %2;" : "=l"(r) : "l"(a), "l"(b)); return r;
}

// ---------------------------------------------------------------------------
// Transpose key_features [B, C, N] -> [B, N, C]
// ---------------------------------------------------------------------------
__global__ void transpose_kernel(const float* __restrict__ in, float* __restrict__ out) {
    __shared__ float tile[32][33];
    const int b  = blockIdx.z;
    const int n0 = blockIdx.x * 32;
    const int c0 = blockIdx.y * 32;
    const float* inb  = in  + (size_t)b * Cc * NQ;
    float*       outb = out + (size_t)b * Cc * NQ;
    const int tx = threadIdx.x;   // 0..31
    const int ty = threadIdx.y;   // 0..7
#pragma unroll
    for (int j = 0; j < 32; j += 8)
        tile[ty + j][tx] = inb[(size_t)(c0 + ty + j) * NQ + (n0 + tx)];
    __syncthreads();
#pragma unroll
    for (int j = 0; j < 32; j += 8)
        outb[(size_t)(n0 + ty + j) * Cc + (c0 + tx)] = tile[tx][ty + j];
}

// ---------------------------------------------------------------------------
// kNN. Bitwise-verified rounding tree (rel_err 0.0), now evaluated 2 keys at
// a time with packed f32x2 (identical IEEE results):
//   cross = fma(qz,kz, fma(qy,ky, rn(qx*kx)))
//   t     = fma(-2, cross, sq)        (== fadd(sq, -2*cross); product exact)
//   d     = rn(t + sk)
// Ties: strict '<' insertion keeps earlier index first (matches top_k).
// ---------------------------------------------------------------------------
#define KCHUNK 2048
#define PAIRS (KCHUNK / 2)    // 1024

__global__ void __launch_bounds__(256, 1)
knn_kernel(const float* __restrict__ qc, const float* __restrict__ kc) {
    __shared__ float4 sA[PAIRS];   // (x0, x1, y0, y1)      16 KB
    __shared__ float4 sB[PAIRS];   // (z0, z1, sk0, sk1)    16 KB

    const int b  = blockIdx.x / (NQ / 256);
    const int n0 = (blockIdx.x % (NQ / 256)) * 256;
    const int n  = n0 + threadIdx.x;

    const float* kcb = kc + (size_t)b * 3 * NK;
    const float* qcb = qc + (size_t)b * 3 * NQ;

    const float qx = qcb[n];
    const float qy = qcb[NQ + n];
    const float qz = qcb[2 * NQ + n];
    const float sq = fmaf(qz, qz, fmaf(qy, qy, __fmul_rn(qx, qx)));

    const uint64_t qx2 = pack2(qx, qx);
    const uint64_t qy2 = pack2(qy, qy);
    const uint64_t qz2 = pack2(qz, qz);
    const uint64_t sq2 = pack2(sq, sq);
    const uint64_t m22 = pack2(-2.0f, -2.0f);

    const uint32_t baseA = smem_u32(sA);
    const uint32_t baseB = smem_u32(sB);

    float bd[KK];
    int   bi[KK];
#pragma unroll
    for (int j = 0; j < KK; j++) { bd[j] = 3.4e38f; bi[j] = 0; }

    for (int chunk = 0; chunk < NK; chunk += KCHUNK) {
        __syncthreads();
        // stage key pairs (two stride-2 loads per plane; L1 absorbs overlap)
        for (int m = threadIdx.x; m < PAIRS; m += 256) {
            const int gm = chunk + 2 * m;
            const float x0 = kcb[gm],          x1 = kcb[gm + 1];
            const float y0 = kcb[NK + gm],     y1 = kcb[NK + gm + 1];
            const float z0 = kcb[2 * NK + gm], z1 = kcb[2 * NK + gm + 1];
            const float s0 = fmaf(z0, z0, fmaf(y0, y0, __fmul_rn(x0, x0)));
            const float s1 = fmaf(z1, z1, fmaf(y1, y1, __fmul_rn(x1, x1)));
            sA[m] = make_float4(x0, x1, y0, y1);
            sB[m] = make_float4(z0, z1, s0, s1);
        }
        __syncthreads();

        for (int p = 0; p < PAIRS; p += 4) {
#pragma unroll
            for (int u = 0; u < 4; u++) {
                uint64_t X01, Y01, Z01, W01;
                lds_v2u64(X01, Y01, baseA + (p + u) * 16);
                lds_v2u64(Z01, W01, baseB + (p + u) * 16);
                uint64_t c2 = mul2(qx2, X01);
                c2 = fma2(qy2, Y01, c2);
                c2 = fma2(qz2, Z01, c2);
                const uint64_t t2 = fma2(m22, c2, sq2);   // sq - 2*cross
                const uint64_t d2 = add2(t2, W01);        // ... + |k|^2
                float d0, d1;
                unpack2(d0, d1, d2);
                if (fminf(d0, d1) < bd[KK - 1]) {         // rare
                    const int i0 = chunk + 2 * (p + u);
                    if (d0 < bd[KK - 1]) {
                        float cd = d0; int ci = i0;
#pragma unroll
                        for (int j = 0; j < KK; j++) {
                            const bool sw = cd < bd[j];
                            const float td = bd[j]; const int ti = bi[j];
                            bd[j] = sw ? cd : td;  bi[j] = sw ? ci : ti;
                            cd    = sw ? td : cd;  ci    = sw ? ti : ci;
                        }
                    }
                    if (d1 < bd[KK - 1]) {
                        float cd = d1; int ci = i0 + 1;
#pragma unroll
                        for (int j = 0; j < KK; j++) {
                            const bool sw = cd < bd[j];
                            const float td = bd[j]; const int ti = bi[j];
                            bd[j] = sw ? cd : td;  bi[j] = sw ? ci : ti;
                            cd    = sw ? td : cd;  ci    = sw ? ti : ci;
                        }
                    }
                }
            }
        }
    }

    int* o = g_idx + ((size_t)b * NQ + n) * KK;
#pragma unroll
    for (int j = 0; j < KK; j++) o[j] = bi[j];
}

// ---------------------------------------------------------------------------
// Output kernel (R12 verbatim): tile = 32 queries x 32 channels; each warp
// owns a channel and writes CONTIGUOUS 1KB spans for both halves.
// ---------------------------------------------------------------------------
#define TQ 32
#define TC 32
#define ROWS (TQ * KK)      // 256
#define SNPAD 260
#define SQPAD 33

__global__ void __launch_bounds__(256, 5)
gather_kernel(const float* __restrict__ qf, float* __restrict__ out) {
    __shared__ float sn[TC * SNPAD];     // 33.3 KB  [c][row]
    __shared__ float sqv[TC * SQPAD];    // 4.2 KB   [c][q]
    __shared__ int   sidx[ROWS];         // 1 KB

    const int bid = blockIdx.x;
    const int b   = bid >> 10;
    const int rem = bid & 1023;
    const int cg  = rem >> 7;
    const int nc  = rem & 127;
    const int c0  = cg * TC;
    const int n0  = nc * TQ;
    const int t   = threadIdx.x;

    sidx[t] = g_idx[((size_t)b * NQ + n0) * KK + t];

#pragma unroll
    for (int it = 0; it < 4; it++) {
        const int cl = (t >> 5) + 8 * it;
        const int q  = t & 31;
        sqv[cl * SQPAD + q] = qf[((size_t)b * Cc + c0 + cl) * NQ + n0 + q];
    }
    __syncthreads();

    const float4* kf4 = reinterpret_cast<const float4*>(g_kf_t);
#pragma unroll
    for (int it = 0; it < 8; it++) {
        const int i  = t + it * 256;
        const int r  = i >> 3;
        const int c4 = i & 7;
        const int row = sidx[r];
        const float4 v = kf4[((size_t)b * NK + row) * (Cc / 4) + cg * 8 + c4];
        sn[(c4 * 4 + 0) * SNPAD + r] = v.x;
        sn[(c4 * 4 + 1) * SNPAD + r] = v.y;
        sn[(c4 * 4 + 2) * SNPAD + r] = v.z;
        sn[(c4 * 4 + 3) * SNPAD + r] = v.w;
    }
    __syncthreads();

    const int w    = t >> 5;
    const int lane = t & 31;

#pragma unroll
    for (int citer = 0; citer < 4; citer++) {
        const int cl = w + 8 * citer;
        const int c  = c0 + cl;
        const size_t baseD = ((size_t)b * (2 * Cc) + c) * ((size_t)NQ * KK) + (size_t)n0 * KK;
        const size_t baseB = ((size_t)b * (2 * Cc) + Cc + c) * ((size_t)NQ * KK) + (size_t)n0 * KK;
#pragma unroll
        for (int j = 0; j < 2; j++) {
            const int p = j * 32 + lane;           // 0..63
            const float4 v = *reinterpret_cast<const float4*>(&sn[cl * SNPAD + 4 * p]);
            const float qv = sqv[cl * SQPAD + (p >> 1)];
            __stcs(reinterpret_cast<float4*>(out + baseD + 4 * p),
                   make_float4(v.x - qv, v.y - qv, v.z - qv, v.w - qv));
            __stcs(reinterpret_cast<float4*>(out + baseB + 4 * p),
                   make_float4(qv, qv, qv, qv));
        }
    }
}

// ---------------------------------------------------------------------------
extern "C" void kernel_launch(void* const* d_in, const int* in_sizes, int n_in,
                              void* d_out, int out_size) {
    const float* query_coords   = (const float*)d_in[0];
    const float* query_features = (const float*)d_in[1];
    const float* key_coords     = (const float*)d_in[2];
    const float* key_features   = (const float*)d_in[3];
    float* out = (float*)d_out;

    float* kf_t; cudaGetSymbolAddress((void**)&kf_t, g_kf_t);

    dim3 tgrid(NQ / 32, Cc / 32, Bq);
    dim3 tblk(32, 8);
    transpose_kernel<<<tgrid, tblk>>>(key_features, kf_t);

    knn_kernel<<<Bq * (NQ / 256), 256>>>(query_coords, key_coords);

    gather_kernel<<<Bq * (Cc / TC) * (NQ / TQ), 256>>>(query_features, out);
}